// round 13
// baseline (speedup 1.0000x reference)
#include <cuda_runtime.h>
#include <cuda_bf16.h>
#include <math.h>
#include <stdint.h>

#define Bsz 4
#define SEQ 2048
#define DM 768
#define NH 12
#define DH 64
#define INTER 1152
#define MROWS (Bsz*SEQ)   // 8192

// ---------------- scratch (allocation-free) ----------------
__device__ float g_qkv[MROWS*3*DM];
__device__ float g_h  [MROWS*DM];
__device__ float g_tmp[MROWS*2*INTER];
__device__ __nv_bfloat16 g_xn_bf [MROWS*DM];
__device__ __nv_bfloat16 g_ctx_bf[MROWS*DM];
__device__ __nv_bfloat16 g_act_bf[MROWS*INTER];
__device__ __nv_bfloat16 g_wqkv_bf[DM*3*DM];
__device__ __nv_bfloat16 g_wo_bf  [DM*DM];
__device__ __nv_bfloat16 g_wi_bf  [DM*2*INTER];
__device__ __nv_bfloat16 g_womlp_bf[INTER*DM];

__device__ __forceinline__ uint32_t f2tf(float f) {
    uint32_t u;
    asm("cvt.rna.tf32.f32 %0, %1;" : "=r"(u) : "f"(f));
    return u;
}
__device__ __forceinline__ void cp16(uint32_t s, const void* g) {
    asm volatile("cp.async.cg.shared.global [%0], [%1], 16;\n" :: "r"(s), "l"(g));
}
#define CP_COMMIT() asm volatile("cp.async.commit_group;\n" ::: "memory")
#define CP_WAIT(n)  asm volatile("cp.async.wait_group %0;\n" :: "n"(n) : "memory")

// ---------------- f32 -> bf16 convert ----------------
__global__ void f2bf_kernel(const float* __restrict__ in, __nv_bfloat16* __restrict__ out, int n) {
    int i = (blockIdx.x * blockDim.x + threadIdx.x) * 4;
    if (i < n) {
        float4 v = *(const float4*)(in + i);
        *(__nv_bfloat162*)(out + i)     = __floats2bfloat162_rn(v.x, v.y);
        *(__nv_bfloat162*)(out + i + 2) = __floats2bfloat162_rn(v.z, v.w);
    }
}

// ---------------- block reduce ----------------
__device__ __forceinline__ float blockReduceSum(float val, float* sh) {
    __syncthreads();
    int lane = threadIdx.x & 31, w = threadIdx.x >> 5;
    #pragma unroll
    for (int o = 16; o; o >>= 1) val += __shfl_xor_sync(0xffffffffu, val, o);
    if (lane == 0) sh[w] = val;
    __syncthreads();
    if (w == 0) {
        float v = (lane < 8) ? sh[lane] : 0.f;
        #pragma unroll
        for (int o = 4; o; o >>= 1) v += __shfl_xor_sync(0xffffffffu, v, o);
        if (lane == 0) sh[0] = v;
    }
    __syncthreads();
    return sh[0];
}

// ---------------- layernorm (fp32 in, bf16 out) ----------------
__global__ void ln_kernel(const float* __restrict__ x, const float* __restrict__ gamma,
                          __nv_bfloat16* __restrict__ out) {
    __shared__ float sh[8];
    int row = blockIdx.x;
    const float* xr = x + (size_t)row * DM;
    int t = threadIdx.x;
    float v[3]; float s = 0.f;
    #pragma unroll
    for (int i = 0; i < 3; i++) { v[i] = xr[t + i*256]; s += v[i]; }
    float tot = blockReduceSum(s, sh);
    float mean = tot * (1.0f/768.0f);
    float s2 = 0.f;
    #pragma unroll
    for (int i = 0; i < 3; i++) { float d = v[i]-mean; s2 += d*d; }
    float tot2 = blockReduceSum(s2, sh);
    float rstd = rsqrtf(tot2 * (1.0f/768.0f) + 1e-5f);
    __nv_bfloat16* orow = out + (size_t)row * DM;
    #pragma unroll
    for (int i = 0; i < 3; i++)
        orow[t + i*256] = __float2bfloat16((v[i]-mean) * rstd * gamma[t + i*256]);
}

// ---------------- BF16 GEMM: 128x256 tile, warp tile 64x64 ----------------
// mma.m16n8k16 + ldmatrix + cp.async 4-stage. 256 thr, 8 warps (2x4).
// B tile = two 128-col panels, each with R11's conflict-free 136h stride.
#define BM 128
#define BN 256
#define BK 32
#define NST 4
#define ASTRh 40
#define BPSTRh 136                       // halves per B panel row
#define PANEL_H (BK*BPSTRh)              // 4352 halves per panel
#define A_STAGE_H (BM*ASTRh)             // 5120
#define B_STAGE_H (2*PANEL_H)            // 8704
#define AOFFh (NST*A_STAGE_H)            // 20480
#define GEMM_SMEM_B ((AOFFh + NST*B_STAGE_H)*2)   // 110592 bytes

__global__ void __launch_bounds__(256, 1)
bf16gemm_kernel(const __nv_bfloat16* __restrict__ A, const __nv_bfloat16* __restrict__ B,
                const float* __restrict__ R, float* __restrict__ C,
                int M, int N, int K, int addres) {
    extern __shared__ __nv_bfloat16 smem[];
    uint32_t sBase = (uint32_t)__cvta_generic_to_shared(smem);

    int tid = threadIdx.x;
    int lane = tid & 31, warp = tid >> 5;
    int wm = warp >> 2, wn = warp & 3;
    int bm = blockIdx.y * BM, bn = blockIdx.x * BN;
    int lr = lane >> 2, lc = lane & 3;

    float acc[4][8][4];
    #pragma unroll
    for (int i = 0; i < 4; i++)
        #pragma unroll
        for (int j = 0; j < 8; j++)
            #pragma unroll
            for (int r = 0; r < 4; r++) acc[i][j][r] = 0.f;

    auto issue = [&](int kblk, int slot) {
        #pragma unroll
        for (int i = 0; i < 2; i++) {          // A: 512 16B chunks
            int c = tid*2 + i;
            int row = c >> 2, koff = (c & 3) * 8;
            const __nv_bfloat16* g = A + (size_t)(bm + row) * K + kblk + koff;
            cp16(sBase + (slot*A_STAGE_H + row*ASTRh + koff)*2, g);
        }
        #pragma unroll
        for (int i = 0; i < 4; i++) {          // B: 1024 16B chunks (2 panels)
            int c = tid*4 + i;
            int panel = c >> 9, rem = c & 511;
            int row = rem >> 4, noff = (rem & 15) * 8;
            const __nv_bfloat16* g = B + (size_t)(kblk + row) * N + bn + panel*128 + noff;
            cp16(sBase + (AOFFh + slot*B_STAGE_H + panel*PANEL_H + row*BPSTRh + noff)*2, g);
        }
    };

    int nk = K / BK;
    #pragma unroll
    for (int s = 0; s < NST-1; s++) { issue(s*BK, s); CP_COMMIT(); }

    int aRowSel = lane & 15;
    int aColSel = (lane >> 4) << 3;
    int bKSel   = (lane & 7) + ((lane >> 4) << 3);
    int bNSel   = ((lane >> 3) & 1) << 3;
    int panel   = wn >> 1;
    int colbase = (wn & 1) * 64;

    for (int s = 0; s < nk; s++) {
        CP_WAIT(NST-2);
        __syncthreads();
        int nxt = s + NST - 1;
        if (nxt < nk) issue(nxt*BK, nxt % NST);
        CP_COMMIT();

        int buf = s % NST;
        uint32_t aBase = sBase + (buf*A_STAGE_H)*2;
        uint32_t bBase = sBase + (AOFFh + buf*B_STAGE_H + panel*PANEL_H)*2;

        #pragma unroll
        for (int ks = 0; ks < 2; ks++) {
            int kb = ks * 16;
            uint32_t af[4][4], bfr[8][2];
            #pragma unroll
            for (int mt = 0; mt < 4; mt++) {
                int row = wm*64 + mt*16 + aRowSel;
                uint32_t addr = aBase + (row*ASTRh + kb + aColSel)*2;
                asm volatile("ldmatrix.sync.aligned.m8n8.x4.shared.b16 {%0,%1,%2,%3}, [%4];"
                    : "=r"(af[mt][0]), "=r"(af[mt][1]), "=r"(af[mt][2]), "=r"(af[mt][3])
                    : "r"(addr));
            }
            #pragma unroll
            for (int g = 0; g < 4; g++) {
                int krow = kb + bKSel;
                int ncol = colbase + g*16 + bNSel;
                uint32_t addr = bBase + (krow*BPSTRh + ncol)*2;
                uint32_t r0, r1, r2, r3;
                asm volatile("ldmatrix.sync.aligned.m8n8.x4.trans.shared.b16 {%0,%1,%2,%3}, [%4];"
                    : "=r"(r0), "=r"(r1), "=r"(r2), "=r"(r3)
                    : "r"(addr));
                bfr[2*g][0]   = r0; bfr[2*g][1]   = r2;
                bfr[2*g+1][0] = r1; bfr[2*g+1][1] = r3;
            }
            #pragma unroll
            for (int mt = 0; mt < 4; mt++)
                #pragma unroll
                for (int nt = 0; nt < 8; nt++) {
                    asm volatile(
                        "mma.sync.aligned.m16n8k16.row.col.f32.bf16.bf16.f32 "
                        "{%0,%1,%2,%3},{%4,%5,%6,%7},{%8,%9},{%0,%1,%2,%3};"
                        : "+f"(acc[mt][nt][0]), "+f"(acc[mt][nt][1]),
                          "+f"(acc[mt][nt][2]), "+f"(acc[mt][nt][3])
                        : "r"(af[mt][0]), "r"(af[mt][1]), "r"(af[mt][2]), "r"(af[mt][3]),
                          "r"(bfr[nt][0]), "r"(bfr[nt][1]));
                }
        }
    }

    #pragma unroll
    for (int mt = 0; mt < 4; mt++) {
        int r0 = bm + wm*64 + mt*16 + lr;
        #pragma unroll
        for (int half = 0; half < 2; half++) {
            int row = r0 + half*8;
            #pragma unroll
            for (int nt = 0; nt < 8; nt++) {
                int col = bn + wn*64 + nt*8 + 2*lc;
                size_t off = (size_t)row * N + col;
                float2 v = make_float2(acc[mt][nt][half*2], acc[mt][nt][half*2+1]);
                if (addres) {
                    float2 rv = *(const float2*)(R + off);
                    v.x += rv.x; v.y += rv.y;
                }
                *(float2*)(C + off) = v;
            }
        }
    }
}

// ---------------- RoPE ----------------
__global__ void rope_kernel(float* __restrict__ qkv) {
    int idx = blockIdx.x * blockDim.x + threadIdx.x;
    if (idx >= MROWS * NH * 32) return;
    int i   = idx & 31;
    int h   = (idx >> 5) % NH;
    int row = idx / (32 * NH);
    int s   = row & (SEQ - 1);
    float invf = expf(-(float)i * (9.210340371976184f / 32.0f));
    float ang = (float)s * invf;
    float c, sn;
    sincosf(ang, &sn, &c);
    size_t base = (size_t)row * (3*DM) + h * DH;
    float* q = qkv + base;
    float* k = qkv + base + DM;
    float q1 = q[i], q2 = q[i+32];
    q[i]    = q1*c - q2*sn;
    q[i+32] = q2*c + q1*sn;
    float k1 = k[i], k2 = k[i+32];
    k[i]    = k1*c - k2*sn;
    k[i+32] = k2*c + k1*sn;
}

// ---------------- TF32 MMA sliding-window attention (bf16 ctx out) --------
#define TQ 64
#define TK 192
#define KSTR 68
#define VSTR 72
#define PSTR 196
#define SM_V_OFF (TK*KSTR)
#define SM_ATTN_W (SM_V_OFF + TK*VSTR)
#define SM_ATTN_BYTES (SM_ATTN_W*4)         // 107520 bytes

__global__ void __launch_bounds__(128, 2)
attn_mma_kernel(const float* __restrict__ qkv, __nv_bfloat16* __restrict__ ctx) {
    extern __shared__ uint32_t sm[];
    uint32_t* Ks = sm;
    uint32_t* Ps = sm;
    uint32_t* Vs = sm + SM_V_OFF;

    int bh = blockIdx.y;
    int b = bh / NH, h = bh % NH;
    int q0 = blockIdx.x * TQ;
    int kc0 = q0 - 64;
    int tid = threadIdx.x, lane = tid & 31, w = tid >> 5;
    int lr = lane >> 2, lc = lane & 3;

    size_t rowQ = (size_t)b * SEQ;
    size_t baseQ = rowQ * (3*DM) + h * DH;
    size_t baseK = baseQ + DM;
    size_t baseV = baseQ + 2*DM;

    uint32_t qf[8][4];
    {
        const float* qp0 = qkv + baseQ + (size_t)(q0 + 16*w + lr) * (3*DM);
        const float* qp1 = qp0 + (size_t)8 * (3*DM);
        #pragma unroll
        for (int k = 0; k < 8; k++) {
            qf[k][0] = f2tf(qp0[8*k + lc]     * 0.125f);
            qf[k][1] = f2tf(qp1[8*k + lc]     * 0.125f);
            qf[k][2] = f2tf(qp0[8*k + 4 + lc] * 0.125f);
            qf[k][3] = f2tf(qp1[8*k + 4 + lc] * 0.125f);
        }
    }

    #pragma unroll
    for (int i = 0; i < 24; i++) {
        int id = tid + i*128;
        int r = id >> 4, c = (id & 15) << 2;
        int kg = kc0 + r;
        float4 kv = make_float4(0,0,0,0), vv = make_float4(0,0,0,0);
        if (kg >= 0 && kg < SEQ) {
            kv = *(const float4*)(qkv + baseK + (size_t)kg*(3*DM) + c);
            vv = *(const float4*)(qkv + baseV + (size_t)kg*(3*DM) + c);
        }
        uint32_t* pk = &Ks[r*KSTR + c];
        pk[0] = f2tf(kv.x); pk[1] = f2tf(kv.y); pk[2] = f2tf(kv.z); pk[3] = f2tf(kv.w);
        uint32_t* pv = &Vs[r*VSTR + c];
        pv[0] = f2tf(vv.x); pv[1] = f2tf(vv.y); pv[2] = f2tf(vv.z); pv[3] = f2tf(vv.w);
    }
    __syncthreads();

    float acc[24][4];
    #pragma unroll
    for (int nt = 0; nt < 24; nt++)
        #pragma unroll
        for (int j = 0; j < 4; j++) acc[nt][j] = 0.f;

    #pragma unroll
    for (int k = 0; k < 8; k++) {
        #pragma unroll
        for (int nt = 0; nt < 24; nt++) {
            uint32_t b0 = Ks[(8*nt + lr)*KSTR + 8*k + lc];
            uint32_t b1 = Ks[(8*nt + lr)*KSTR + 8*k + 4 + lc];
            asm volatile(
                "mma.sync.aligned.m16n8k8.row.col.f32.tf32.tf32.f32 "
                "{%0,%1,%2,%3},{%4,%5,%6,%7},{%8,%9},{%0,%1,%2,%3};"
                : "+f"(acc[nt][0]), "+f"(acc[nt][1]), "+f"(acc[nt][2]), "+f"(acc[nt][3])
                : "r"(qf[k][0]), "r"(qf[k][1]), "r"(qf[k][2]), "r"(qf[k][3]),
                  "r"(b0), "r"(b1));
        }
    }

    int r0 = 16*w + lr, r1 = r0 + 8;
    int cl0 = (q0 == 0) ? 64 : 0;
    int cl1 = SEQ - 1 - kc0; if (cl1 > 191) cl1 = 191;
    int lo0 = r0 > cl0 ? r0 : cl0;  int hi0 = (r0+128) < cl1 ? (r0+128) : cl1;
    int lo1 = r1 > cl0 ? r1 : cl0;  int hi1 = (r1+128) < cl1 ? (r1+128) : cl1;

    float m0 = -1e30f, m1 = -1e30f;
    #pragma unroll
    for (int nt = 0; nt < 24; nt++) {
        int c = 8*nt + 2*lc;
        if (c   >= lo0 && c   <= hi0) m0 = fmaxf(m0, acc[nt][0]);
        if (c+1 >= lo0 && c+1 <= hi0) m0 = fmaxf(m0, acc[nt][1]);
        if (c   >= lo1 && c   <= hi1) m1 = fmaxf(m1, acc[nt][2]);
        if (c+1 >= lo1 && c+1 <= hi1) m1 = fmaxf(m1, acc[nt][3]);
    }
    #pragma unroll
    for (int o = 1; o <= 2; o <<= 1) {
        m0 = fmaxf(m0, __shfl_xor_sync(0xffffffffu, m0, o));
        m1 = fmaxf(m1, __shfl_xor_sync(0xffffffffu, m1, o));
    }
    float l0 = 0.f, l1 = 0.f;
    #pragma unroll
    for (int nt = 0; nt < 24; nt++) {
        int c = 8*nt + 2*lc;
        float p;
        p = (c   >= lo0 && c   <= hi0) ? __expf(acc[nt][0] - m0) : 0.f; acc[nt][0] = p; l0 += p;
        p = (c+1 >= lo0 && c+1 <= hi0) ? __expf(acc[nt][1] - m0) : 0.f; acc[nt][1] = p; l0 += p;
        p = (c   >= lo1 && c   <= hi1) ? __expf(acc[nt][2] - m1) : 0.f; acc[nt][2] = p; l1 += p;
        p = (c+1 >= lo1 && c+1 <= hi1) ? __expf(acc[nt][3] - m1) : 0.f; acc[nt][3] = p; l1 += p;
    }
    #pragma unroll
    for (int o = 1; o <= 2; o <<= 1) {
        l0 += __shfl_xor_sync(0xffffffffu, l0, o);
        l1 += __shfl_xor_sync(0xffffffffu, l1, o);
    }
    float inv0 = 1.0f / l0, inv1 = 1.0f / l1;

    __syncthreads();

    #pragma unroll
    for (int nt = 0; nt < 24; nt++) {
        int c = 8*nt + 2*lc;
        uint32_t* pr0 = &Ps[r0*PSTR + c];
        pr0[0] = f2tf(acc[nt][0] * inv0);
        pr0[1] = f2tf(acc[nt][1] * inv0);
        uint32_t* pr1 = &Ps[r1*PSTR + c];
        pr1[0] = f2tf(acc[nt][2] * inv1);
        pr1[1] = f2tf(acc[nt][3] * inv1);
    }
    __syncthreads();

    float o[8][4];
    #pragma unroll
    for (int nt = 0; nt < 8; nt++)
        #pragma unroll
        for (int j = 0; j < 4; j++) o[nt][j] = 0.f;

    const uint32_t* pb = &Ps[(16*w + lr)*PSTR + lc];
    #pragma unroll
    for (int kc = 0; kc < 24; kc++) {
        uint32_t a0 = pb[kc*8];
        uint32_t a1 = pb[8*PSTR + kc*8];
        uint32_t a2 = pb[kc*8 + 4];
        uint32_t a3 = pb[8*PSTR + kc*8 + 4];
        #pragma unroll
        for (int nt = 0; nt < 8; nt++) {
            uint32_t b0 = Vs[(8*kc + lc)*VSTR + 8*nt + lr];
            uint32_t b1 = Vs[(8*kc + 4 + lc)*VSTR + 8*nt + lr];
            asm volatile(
                "mma.sync.aligned.m16n8k8.row.col.f32.tf32.tf32.f32 "
                "{%0,%1,%2,%3},{%4,%5,%6,%7},{%8,%9},{%0,%1,%2,%3};"
                : "+f"(o[nt][0]), "+f"(o[nt][1]), "+f"(o[nt][2]), "+f"(o[nt][3])
                : "r"(a0), "r"(a1), "r"(a2), "r"(a3), "r"(b0), "r"(b1));
        }
    }

    size_t baseO = rowQ * DM + h * DH;
    int row0 = q0 + 16*w + lr;
    #pragma unroll
    for (int nt = 0; nt < 8; nt++) {
        int col = 8*nt + 2*lc;
        *(__nv_bfloat162*)(ctx + baseO + (size_t)row0 * DM + col)
            = __floats2bfloat162_rn(o[nt][0], o[nt][1]);
        *(__nv_bfloat162*)(ctx + baseO + (size_t)(row0+8) * DM + col)
            = __floats2bfloat162_rn(o[nt][2], o[nt][3]);
    }
}

// ---------------- GLU (fp32 in, bf16 out) ----------------
__global__ void glu_kernel(const float* __restrict__ t, __nv_bfloat16* __restrict__ act) {
    int idx = blockIdx.x * blockDim.x + threadIdx.x;
    if (idx >= MROWS * INTER) return;
    int row = idx / INTER, col = idx - row * INTER;
    float x = t[(size_t)row * (2*INTER) + col];
    float g = t[(size_t)row * (2*INTER) + INTER + col];
    act[idx] = __float2bfloat16(x * normcdff(x) * g);
}

// ---------------- launch ----------------
extern "C" void kernel_launch(void* const* d_in, const int* in_sizes, int n_in,
                              void* d_out, int out_size) {
    const float* hidden  = (const float*)d_in[0];
    const float* gamma1  = (const float*)d_in[2];
    const float* wqkv    = (const float*)d_in[3];
    const float* wo_attn = (const float*)d_in[4];
    const float* gamma2  = (const float*)d_in[5];
    const float* wi      = (const float*)d_in[6];
    const float* wo_mlp  = (const float*)d_in[7];
    float* out = (float*)d_out;

    static float *p_qkv=nullptr, *p_h, *p_tmp;
    static __nv_bfloat16 *p_xn, *p_ctx, *p_act, *p_wqkv, *p_wo, *p_wi, *p_womlp;
    if (!p_qkv) {
        cudaGetSymbolAddress((void**)&p_qkv, g_qkv);
        cudaGetSymbolAddress((void**)&p_h,   g_h);
        cudaGetSymbolAddress((void**)&p_tmp, g_tmp);
        cudaGetSymbolAddress((void**)&p_xn,  g_xn_bf);
        cudaGetSymbolAddress((void**)&p_ctx, g_ctx_bf);
        cudaGetSymbolAddress((void**)&p_act, g_act_bf);
        cudaGetSymbolAddress((void**)&p_wqkv, g_wqkv_bf);
        cudaGetSymbolAddress((void**)&p_wo,   g_wo_bf);
        cudaGetSymbolAddress((void**)&p_wi,   g_wi_bf);
        cudaGetSymbolAddress((void**)&p_womlp, g_womlp_bf);
        cudaFuncSetAttribute(attn_mma_kernel,
                             cudaFuncAttributeMaxDynamicSharedMemorySize, SM_ATTN_BYTES);
        cudaFuncSetAttribute(bf16gemm_kernel,
                             cudaFuncAttributeMaxDynamicSharedMemorySize, GEMM_SMEM_B);
    }

    f2bf_kernel<<<(DM*3*DM/4 + 255)/256, 256>>>(wqkv, p_wqkv, DM*3*DM);
    f2bf_kernel<<<(DM*DM/4 + 255)/256, 256>>>(wo_attn, p_wo, DM*DM);
    f2bf_kernel<<<(DM*2*INTER/4 + 255)/256, 256>>>(wi, p_wi, DM*2*INTER);
    f2bf_kernel<<<(INTER*DM/4 + 255)/256, 256>>>(wo_mlp, p_womlp, INTER*DM);

    ln_kernel<<<MROWS, 256>>>(hidden, gamma1, p_xn);
    bf16gemm_kernel<<<dim3(2304/BN, MROWS/BM), 256, GEMM_SMEM_B>>>(p_xn, p_wqkv, nullptr, p_qkv,
                                                                   MROWS, 3*DM, DM, 0);
    {
        int n = MROWS * NH * 32;
        rope_kernel<<<(n + 255)/256, 256>>>(p_qkv);
    }
    attn_mma_kernel<<<dim3(SEQ/TQ, Bsz*NH), 128, SM_ATTN_BYTES>>>(p_qkv, p_ctx);
    bf16gemm_kernel<<<dim3(768/BN, MROWS/BM), 256, GEMM_SMEM_B>>>(p_ctx, p_wo, hidden, p_h,
                                                                  MROWS, DM, DM, 1);
    ln_kernel<<<MROWS, 256>>>(p_h, gamma2, p_xn);
    bf16gemm_kernel<<<dim3(2304/BN, MROWS/BM), 256, GEMM_SMEM_B>>>(p_xn, p_wi, nullptr, p_tmp,
                                                                   MROWS, 2*INTER, DM, 0);
    {
        int n = MROWS * INTER;
        glu_kernel<<<(n + 255)/256, 256>>>(p_tmp, p_act);
    }
    bf16gemm_kernel<<<dim3(768/BN, MROWS/BM), 256, GEMM_SMEM_B>>>(p_act, p_womlp, p_h, out,
                                                                  MROWS, DM, INTER, 1);
}

// round 15
// speedup vs baseline: 1.8427x; 1.8427x over previous
#include <cuda_runtime.h>
#include <cuda_bf16.h>
#include <math.h>
#include <stdint.h>

#define Bsz 4
#define SEQ 2048
#define DM 768
#define NH 12
#define DH 64
#define INTER 1152
#define MROWS (Bsz*SEQ)   // 8192

// ---------------- scratch (allocation-free) ----------------
__device__ float g_qkv[MROWS*3*DM];
__device__ float g_h  [MROWS*DM];
__device__ float g_tmp[MROWS*INTER];            // x half of wi output (fp32)
__device__ __nv_bfloat16 g_xn_bf [MROWS*DM];
__device__ __nv_bfloat16 g_ctx_bf[MROWS*DM];
__device__ __nv_bfloat16 g_act_bf[MROWS*INTER];
__device__ __nv_bfloat16 g_wqkv_bf[DM*3*DM];
__device__ __nv_bfloat16 g_wo_bf  [DM*DM];
__device__ __nv_bfloat16 g_wi_bf  [DM*2*INTER];
__device__ __nv_bfloat16 g_womlp_bf[INTER*DM];

__device__ __forceinline__ uint32_t f2tf(float f) {
    uint32_t u;
    asm("cvt.rna.tf32.f32 %0, %1;" : "=r"(u) : "f"(f));
    return u;
}
__device__ __forceinline__ void cp16(uint32_t s, const void* g) {
    asm volatile("cp.async.cg.shared.global [%0], [%1], 16;\n" :: "r"(s), "l"(g));
}
#define CP_COMMIT() asm volatile("cp.async.commit_group;\n" ::: "memory")
#define CP_WAIT(n)  asm volatile("cp.async.wait_group %0;\n" :: "n"(n) : "memory")

// ---------------- merged weight convert (all 4 weights, one launch) -------
#define WC_S1 (DM*3*DM)          // 1769472
#define WC_S2 (DM*DM)            // 589824
#define WC_S3 (DM*2*INTER)       // 1769472
#define WC_S4 (INTER*DM)         // 884736
#define WC_TOTAL (WC_S1+WC_S2+WC_S3+WC_S4)

__global__ void wconv_kernel(const float* __restrict__ w1, const float* __restrict__ w2,
                             const float* __restrict__ w3, const float* __restrict__ w4,
                             __nv_bfloat16* __restrict__ o1, __nv_bfloat16* __restrict__ o2,
                             __nv_bfloat16* __restrict__ o3, __nv_bfloat16* __restrict__ o4) {
    int i = (blockIdx.x * blockDim.x + threadIdx.x) * 4;
    if (i >= WC_TOTAL) return;
    const float* in; __nv_bfloat16* out; int off;
    if (i < WC_S1)                       { in = w1; out = o1; off = i; }
    else if (i < WC_S1+WC_S2)            { in = w2; out = o2; off = i - WC_S1; }
    else if (i < WC_S1+WC_S2+WC_S3)      { in = w3; out = o3; off = i - WC_S1 - WC_S2; }
    else                                 { in = w4; out = o4; off = i - WC_S1 - WC_S2 - WC_S3; }
    float4 v = *(const float4*)(in + off);
    *(__nv_bfloat162*)(out + off)     = __floats2bfloat162_rn(v.x, v.y);
    *(__nv_bfloat162*)(out + off + 2) = __floats2bfloat162_rn(v.z, v.w);
}

// ---------------- block reduce ----------------
__device__ __forceinline__ float blockReduceSum(float val, float* sh) {
    __syncthreads();
    int lane = threadIdx.x & 31, w = threadIdx.x >> 5;
    #pragma unroll
    for (int o = 16; o; o >>= 1) val += __shfl_xor_sync(0xffffffffu, val, o);
    if (lane == 0) sh[w] = val;
    __syncthreads();
    if (w == 0) {
        float v = (lane < 8) ? sh[lane] : 0.f;
        #pragma unroll
        for (int o = 4; o; o >>= 1) v += __shfl_xor_sync(0xffffffffu, v, o);
        if (lane == 0) sh[0] = v;
    }
    __syncthreads();
    return sh[0];
}

// ---------------- layernorm (fp32 in, bf16 out) ----------------
__global__ void ln_kernel(const float* __restrict__ x, const float* __restrict__ gamma,
                          __nv_bfloat16* __restrict__ out) {
    __shared__ float sh[8];
    int row = blockIdx.x;
    const float* xr = x + (size_t)row * DM;
    int t = threadIdx.x;
    float v[3]; float s = 0.f;
    #pragma unroll
    for (int i = 0; i < 3; i++) { v[i] = xr[t + i*256]; s += v[i]; }
    float tot = blockReduceSum(s, sh);
    float mean = tot * (1.0f/768.0f);
    float s2 = 0.f;
    #pragma unroll
    for (int i = 0; i < 3; i++) { float d = v[i]-mean; s2 += d*d; }
    float tot2 = blockReduceSum(s2, sh);
    float rstd = rsqrtf(tot2 * (1.0f/768.0f) + 1e-5f);
    __nv_bfloat16* orow = out + (size_t)row * DM;
    #pragma unroll
    for (int i = 0; i < 3; i++)
        orow[t + i*256] = __float2bfloat16((v[i]-mean) * rstd * gamma[t + i*256]);
}

// ---------------- BF16 GEMM (R11-proven): 128x128, warp 64x32, 4-stage ----
// mode 0: C fp32 = AB     mode 1: C fp32 = AB + R     mode 2: C bf16 = gelu(R)*AB
#define BM 128
#define BN 128
#define BK 32
#define NST 4
#define ASTRh 40
#define BSTRh 136
#define A_STAGE_H (BM*ASTRh)
#define B_STAGE_H (BK*BSTRh)
#define AOFFh (NST*A_STAGE_H)
#define GEMM_SMEM_B ((AOFFh + NST*B_STAGE_H)*2)   // 75776 bytes

__global__ void __launch_bounds__(256, 2)
bf16gemm_kernel(const __nv_bfloat16* __restrict__ A, const __nv_bfloat16* __restrict__ B,
                const float* __restrict__ R, void* __restrict__ Cv,
                int M, int N, int K, int ldB, int mode) {
    extern __shared__ __nv_bfloat16 smem[];
    uint32_t sBase = (uint32_t)__cvta_generic_to_shared(smem);

    int tid = threadIdx.x;
    int lane = tid & 31, warp = tid >> 5;
    int wm = warp >> 2, wn = warp & 3;
    int bm = blockIdx.y * BM, bn = blockIdx.x * BN;
    int lr = lane >> 2, lc = lane & 3;

    float acc[4][4][4];
    #pragma unroll
    for (int i = 0; i < 4; i++)
        #pragma unroll
        for (int j = 0; j < 4; j++)
            #pragma unroll
            for (int r = 0; r < 4; r++) acc[i][j][r] = 0.f;

    auto issue = [&](int kblk, int slot) {
        #pragma unroll
        for (int i = 0; i < 2; i++) {
            int c = tid*2 + i;
            int row = c >> 2, koff = (c & 3) * 8;
            const __nv_bfloat16* g = A + (size_t)(bm + row) * K + kblk + koff;
            cp16(sBase + (slot*A_STAGE_H + row*ASTRh + koff)*2, g);
        }
        #pragma unroll
        for (int i = 0; i < 2; i++) {
            int c = tid*2 + i;
            int row = c >> 4, noff = (c & 15) * 8;
            const __nv_bfloat16* g = B + (size_t)(kblk + row) * ldB + bn + noff;
            cp16(sBase + (AOFFh + slot*B_STAGE_H + row*BSTRh + noff)*2, g);
        }
    };

    int nk = K / BK;
    #pragma unroll
    for (int s = 0; s < NST-1; s++) { issue(s*BK, s); CP_COMMIT(); }

    int aRowSel = lane & 15;
    int aColSel = (lane >> 4) << 3;
    int bKSel   = (lane & 7) + ((lane >> 4) << 3);
    int bNSel   = ((lane >> 3) & 1) << 3;

    for (int s = 0; s < nk; s++) {
        CP_WAIT(NST-2);
        __syncthreads();
        int nxt = s + NST - 1;
        if (nxt < nk) issue(nxt*BK, nxt % NST);
        CP_COMMIT();

        int buf = s % NST;
        uint32_t aBase = sBase + (buf*A_STAGE_H)*2;
        uint32_t bBase = sBase + (AOFFh + buf*B_STAGE_H)*2;

        #pragma unroll
        for (int ks = 0; ks < 2; ks++) {
            int kb = ks * 16;
            uint32_t af[4][4], bfr[4][2];
            #pragma unroll
            for (int mt = 0; mt < 4; mt++) {
                int row = wm*64 + mt*16 + aRowSel;
                uint32_t addr = aBase + (row*ASTRh + kb + aColSel)*2;
                asm volatile("ldmatrix.sync.aligned.m8n8.x4.shared.b16 {%0,%1,%2,%3}, [%4];"
                    : "=r"(af[mt][0]), "=r"(af[mt][1]), "=r"(af[mt][2]), "=r"(af[mt][3])
                    : "r"(addr));
            }
            #pragma unroll
            for (int ntp = 0; ntp < 2; ntp++) {
                int krow = kb + bKSel;
                int ncol = wn*32 + ntp*16 + bNSel;
                uint32_t addr = bBase + (krow*BSTRh + ncol)*2;
                uint32_t r0, r1, r2, r3;
                asm volatile("ldmatrix.sync.aligned.m8n8.x4.trans.shared.b16 {%0,%1,%2,%3}, [%4];"
                    : "=r"(r0), "=r"(r1), "=r"(r2), "=r"(r3)
                    : "r"(addr));
                bfr[2*ntp][0]   = r0; bfr[2*ntp][1]   = r2;
                bfr[2*ntp+1][0] = r1; bfr[2*ntp+1][1] = r3;
            }
            #pragma unroll
            for (int mt = 0; mt < 4; mt++)
                #pragma unroll
                for (int nt = 0; nt < 4; nt++) {
                    asm volatile(
                        "mma.sync.aligned.m16n8k16.row.col.f32.bf16.bf16.f32 "
                        "{%0,%1,%2,%3},{%4,%5,%6,%7},{%8,%9},{%0,%1,%2,%3};"
                        : "+f"(acc[mt][nt][0]), "+f"(acc[mt][nt][1]),
                          "+f"(acc[mt][nt][2]), "+f"(acc[mt][nt][3])
                        : "r"(af[mt][0]), "r"(af[mt][1]), "r"(af[mt][2]), "r"(af[mt][3]),
                          "r"(bfr[nt][0]), "r"(bfr[nt][1]));
                }
        }
    }

    #pragma unroll
    for (int mt = 0; mt < 4; mt++) {
        int r0 = bm + wm*64 + mt*16 + lr;
        #pragma unroll
        for (int half = 0; half < 2; half++) {
            int row = r0 + half*8;
            #pragma unroll
            for (int nt = 0; nt < 4; nt++) {
                int col = bn + wn*32 + nt*8 + 2*lc;
                size_t off = (size_t)row * N + col;
                float a0 = acc[mt][nt][half*2], a1 = acc[mt][nt][half*2+1];
                if (mode == 2) {
                    float2 xv = *(const float2*)(R + off);
                    float v0 = xv.x * normcdff(xv.x) * a0;
                    float v1 = xv.y * normcdff(xv.y) * a1;
                    *(__nv_bfloat162*)((__nv_bfloat16*)Cv + off)
                        = __floats2bfloat162_rn(v0, v1);
                } else {
                    if (mode == 1) {
                        float2 rv = *(const float2*)(R + off);
                        a0 += rv.x; a1 += rv.y;
                    }
                    *(float2*)((float*)Cv + off) = make_float2(a0, a1);
                }
            }
        }
    }
}

// ---------------- RoPE ----------------
__global__ void rope_kernel(float* __restrict__ qkv) {
    int idx = blockIdx.x * blockDim.x + threadIdx.x;
    if (idx >= MROWS * NH * 32) return;
    int i   = idx & 31;
    int h   = (idx >> 5) % NH;
    int row = idx / (32 * NH);
    int s   = row & (SEQ - 1);
    float invf = expf(-(float)i * (9.210340371976184f / 32.0f));
    float ang = (float)s * invf;
    float c, sn;
    sincosf(ang, &sn, &c);
    size_t base = (size_t)row * (3*DM) + h * DH;
    float* q = qkv + base;
    float* k = qkv + base + DM;
    float q1 = q[i], q2 = q[i+32];
    q[i]    = q1*c - q2*sn;
    q[i+32] = q2*c + q1*sn;
    float k1 = k[i], k2 = k[i+32];
    k[i]    = k1*c - k2*sn;
    k[i+32] = k2*c + k1*sn;
}

// ---------------- TF32 MMA sliding-window attention (bf16 ctx out) --------
#define TQ 64
#define TK 192
#define KSTR 68
#define VSTR 72
#define PSTR 196
#define SM_V_OFF (TK*KSTR)
#define SM_ATTN_W (SM_V_OFF + TK*VSTR)
#define SM_ATTN_BYTES (SM_ATTN_W*4)         // 107520 bytes

__global__ void __launch_bounds__(128, 2)
attn_mma_kernel(const float* __restrict__ qkv, __nv_bfloat16* __restrict__ ctx) {
    extern __shared__ uint32_t sm[];
    uint32_t* Ks = sm;
    uint32_t* Ps = sm;
    uint32_t* Vs = sm + SM_V_OFF;

    int bh = blockIdx.y;
    int b = bh / NH, h = bh % NH;
    int q0 = blockIdx.x * TQ;
    int kc0 = q0 - 64;
    int tid = threadIdx.x, lane = tid & 31, w = tid >> 5;
    int lr = lane >> 2, lc = lane & 3;

    size_t rowQ = (size_t)b * SEQ;
    size_t baseQ = rowQ * (3*DM) + h * DH;
    size_t baseK = baseQ + DM;
    size_t baseV = baseQ + 2*DM;

    uint32_t qf[8][4];
    {
        const float* qp0 = qkv + baseQ + (size_t)(q0 + 16*w + lr) * (3*DM);
        const float* qp1 = qp0 + (size_t)8 * (3*DM);
        #pragma unroll
        for (int k = 0; k < 8; k++) {
            qf[k][0] = f2tf(qp0[8*k + lc]     * 0.125f);
            qf[k][1] = f2tf(qp1[8*k + lc]     * 0.125f);
            qf[k][2] = f2tf(qp0[8*k + 4 + lc] * 0.125f);
            qf[k][3] = f2tf(qp1[8*k + 4 + lc] * 0.125f);
        }
    }

    #pragma unroll
    for (int i = 0; i < 24; i++) {
        int id = tid + i*128;
        int r = id >> 4, c = (id & 15) << 2;
        int kg = kc0 + r;
        float4 kv = make_float4(0,0,0,0), vv = make_float4(0,0,0,0);
        if (kg >= 0 && kg < SEQ) {
            kv = *(const float4*)(qkv + baseK + (size_t)kg*(3*DM) + c);
            vv = *(const float4*)(qkv + baseV + (size_t)kg*(3*DM) + c);
        }
        uint32_t* pk = &Ks[r*KSTR + c];
        pk[0] = f2tf(kv.x); pk[1] = f2tf(kv.y); pk[2] = f2tf(kv.z); pk[3] = f2tf(kv.w);
        uint32_t* pv = &Vs[r*VSTR + c];
        pv[0] = f2tf(vv.x); pv[1] = f2tf(vv.y); pv[2] = f2tf(vv.z); pv[3] = f2tf(vv.w);
    }
    __syncthreads();

    float acc[24][4];
    #pragma unroll
    for (int nt = 0; nt < 24; nt++)
        #pragma unroll
        for (int j = 0; j < 4; j++) acc[nt][j] = 0.f;

    #pragma unroll
    for (int k = 0; k < 8; k++) {
        #pragma unroll
        for (int nt = 0; nt < 24; nt++) {
            uint32_t b0 = Ks[(8*nt + lr)*KSTR + 8*k + lc];
            uint32_t b1 = Ks[(8*nt + lr)*KSTR + 8*k + 4 + lc];
            asm volatile(
                "mma.sync.aligned.m16n8k8.row.col.f32.tf32.tf32.f32 "
                "{%0,%1,%2,%3},{%4,%5,%6,%7},{%8,%9},{%0,%1,%2,%3};"
                : "+f"(acc[nt][0]), "+f"(acc[nt][1]), "+f"(acc[nt][2]), "+f"(acc[nt][3])
                : "r"(qf[k][0]), "r"(qf[k][1]), "r"(qf[k][2]), "r"(qf[k][3]),
                  "r"(b0), "r"(b1));
        }
    }

    int r0 = 16*w + lr, r1 = r0 + 8;
    int cl0 = (q0 == 0) ? 64 : 0;
    int cl1 = SEQ - 1 - kc0; if (cl1 > 191) cl1 = 191;
    int lo0 = r0 > cl0 ? r0 : cl0;  int hi0 = (r0+128) < cl1 ? (r0+128) : cl1;
    int lo1 = r1 > cl0 ? r1 : cl0;  int hi1 = (r1+128) < cl1 ? (r1+128) : cl1;

    float m0 = -1e30f, m1 = -1e30f;
    #pragma unroll
    for (int nt = 0; nt < 24; nt++) {
        int c = 8*nt + 2*lc;
        if (c   >= lo0 && c   <= hi0) m0 = fmaxf(m0, acc[nt][0]);
        if (c+1 >= lo0 && c+1 <= hi0) m0 = fmaxf(m0, acc[nt][1]);
        if (c   >= lo1 && c   <= hi1) m1 = fmaxf(m1, acc[nt][2]);
        if (c+1 >= lo1 && c+1 <= hi1) m1 = fmaxf(m1, acc[nt][3]);
    }
    #pragma unroll
    for (int o = 1; o <= 2; o <<= 1) {
        m0 = fmaxf(m0, __shfl_xor_sync(0xffffffffu, m0, o));
        m1 = fmaxf(m1, __shfl_xor_sync(0xffffffffu, m1, o));
    }
    float l0 = 0.f, l1 = 0.f;
    #pragma unroll
    for (int nt = 0; nt < 24; nt++) {
        int c = 8*nt + 2*lc;
        float p;
        p = (c   >= lo0 && c   <= hi0) ? __expf(acc[nt][0] - m0) : 0.f; acc[nt][0] = p; l0 += p;
        p = (c+1 >= lo0 && c+1 <= hi0) ? __expf(acc[nt][1] - m0) : 0.f; acc[nt][1] = p; l0 += p;
        p = (c   >= lo1 && c   <= hi1) ? __expf(acc[nt][2] - m1) : 0.f; acc[nt][2] = p; l1 += p;
        p = (c+1 >= lo1 && c+1 <= hi1) ? __expf(acc[nt][3] - m1) : 0.f; acc[nt][3] = p; l1 += p;
    }
    #pragma unroll
    for (int o = 1; o <= 2; o <<= 1) {
        l0 += __shfl_xor_sync(0xffffffffu, l0, o);
        l1 += __shfl_xor_sync(0xffffffffu, l1, o);
    }
    float inv0 = 1.0f / l0, inv1 = 1.0f / l1;

    __syncthreads();

    #pragma unroll
    for (int nt = 0; nt < 24; nt++) {
        int c = 8*nt + 2*lc;
        uint32_t* pr0 = &Ps[r0*PSTR + c];
        pr0[0] = f2tf(acc[nt][0] * inv0);
        pr0[1] = f2tf(acc[nt][1] * inv0);
        uint32_t* pr1 = &Ps[r1*PSTR + c];
        pr1[0] = f2tf(acc[nt][2] * inv1);
        pr1[1] = f2tf(acc[nt][3] * inv1);
    }
    __syncthreads();

    float o[8][4];
    #pragma unroll
    for (int nt = 0; nt < 8; nt++)
        #pragma unroll
        for (int j = 0; j < 4; j++) o[nt][j] = 0.f;

    const uint32_t* pb = &Ps[(16*w + lr)*PSTR + lc];
    #pragma unroll
    for (int kc = 0; kc < 24; kc++) {
        uint32_t a0 = pb[kc*8];
        uint32_t a1 = pb[8*PSTR + kc*8];
        uint32_t a2 = pb[kc*8 + 4];
        uint32_t a3 = pb[8*PSTR + kc*8 + 4];
        #pragma unroll
        for (int nt = 0; nt < 8; nt++) {
            uint32_t b0 = Vs[(8*kc + lc)*VSTR + 8*nt + lr];
            uint32_t b1 = Vs[(8*kc + 4 + lc)*VSTR + 8*nt + lr];
            asm volatile(
                "mma.sync.aligned.m16n8k8.row.col.f32.tf32.tf32.f32 "
                "{%0,%1,%2,%3},{%4,%5,%6,%7},{%8,%9},{%0,%1,%2,%3};"
                : "+f"(o[nt][0]), "+f"(o[nt][1]), "+f"(o[nt][2]), "+f"(o[nt][3])
                : "r"(a0), "r"(a1), "r"(a2), "r"(a3), "r"(b0), "r"(b1));
        }
    }

    size_t baseO = rowQ * DM + h * DH;
    int row0 = q0 + 16*w + lr;
    #pragma unroll
    for (int nt = 0; nt < 8; nt++) {
        int col = 8*nt + 2*lc;
        *(__nv_bfloat162*)(ctx + baseO + (size_t)row0 * DM + col)
            = __floats2bfloat162_rn(o[nt][0], o[nt][1]);
        *(__nv_bfloat162*)(ctx + baseO + (size_t)(row0+8) * DM + col)
            = __floats2bfloat162_rn(o[nt][2], o[nt][3]);
    }
}

// ---------------- launch ----------------
extern "C" void kernel_launch(void* const* d_in, const int* in_sizes, int n_in,
                              void* d_out, int out_size) {
    const float* hidden  = (const float*)d_in[0];
    const float* gamma1  = (const float*)d_in[2];
    const float* wqkv    = (const float*)d_in[3];
    const float* wo_attn = (const float*)d_in[4];
    const float* gamma2  = (const float*)d_in[5];
    const float* wi      = (const float*)d_in[6];
    const float* wo_mlp  = (const float*)d_in[7];
    float* out = (float*)d_out;

    static float *p_qkv=nullptr, *p_h, *p_tmp;
    static __nv_bfloat16 *p_xn, *p_ctx, *p_act, *p_wqkv, *p_wo, *p_wi, *p_womlp;
    if (!p_qkv) {
        cudaGetSymbolAddress((void**)&p_qkv, g_qkv);
        cudaGetSymbolAddress((void**)&p_h,   g_h);
        cudaGetSymbolAddress((void**)&p_tmp, g_tmp);
        cudaGetSymbolAddress((void**)&p_xn,  g_xn_bf);
        cudaGetSymbolAddress((void**)&p_ctx, g_ctx_bf);
        cudaGetSymbolAddress((void**)&p_act, g_act_bf);
        cudaGetSymbolAddress((void**)&p_wqkv, g_wqkv_bf);
        cudaGetSymbolAddress((void**)&p_wo,   g_wo_bf);
        cudaGetSymbolAddress((void**)&p_wi,   g_wi_bf);
        cudaGetSymbolAddress((void**)&p_womlp, g_womlp_bf);
        cudaFuncSetAttribute(attn_mma_kernel,
                             cudaFuncAttributeMaxDynamicSharedMemorySize, SM_ATTN_BYTES);
        cudaFuncSetAttribute(bf16gemm_kernel,
                             cudaFuncAttributeMaxDynamicSharedMemorySize, GEMM_SMEM_B);
    }

    // 1) all weight converts in one launch
    wconv_kernel<<<(WC_TOTAL/4 + 255)/256, 256>>>(wqkv, wo_attn, wi, wo_mlp,
                                                  p_wqkv, p_wo, p_wi, p_womlp);
    // 2) pre-attn LN
    ln_kernel<<<MROWS, 256>>>(hidden, gamma1, p_xn);
    // 3) QKV
    bf16gemm_kernel<<<dim3(2304/BN, MROWS/BM), 256, GEMM_SMEM_B>>>(
        p_xn, p_wqkv, nullptr, p_qkv, MROWS, 3*DM, DM, 3*DM, 0);
    // 4) RoPE
    {
        int n = MROWS * NH * 32;
        rope_kernel<<<(n + 255)/256, 256>>>(p_qkv);
    }
    // 5) attention
    attn_mma_kernel<<<dim3(SEQ/TQ, Bsz*NH), 128, SM_ATTN_BYTES>>>(p_qkv, p_ctx);
    // 6) out-proj + residual
    bf16gemm_kernel<<<dim3(DM/BN, MROWS/BM), 256, GEMM_SMEM_B>>>(
        p_ctx, p_wo, hidden, p_h, MROWS, DM, DM, DM, 1);
    // 7) pre-MLP LN
    ln_kernel<<<MROWS, 256>>>(p_h, gamma2, p_xn);
    // 8) wi x-half -> g_tmp (fp32)
    bf16gemm_kernel<<<dim3(INTER/BN, MROWS/BM), 256, GEMM_SMEM_B>>>(
        p_xn, p_wi, nullptr, p_tmp, MROWS, INTER, DM, 2*INTER, 0);
    // 9) wi gate-half + fused GLU -> act (bf16)
    bf16gemm_kernel<<<dim3(INTER/BN, MROWS/BM), 256, GEMM_SMEM_B>>>(
        p_xn, p_wi + INTER, p_tmp, p_act, MROWS, INTER, DM, 2*INTER, 2);
    // 10) wo_mlp + residual -> out
    bf16gemm_kernel<<<dim3(DM/BN, MROWS/BM), 256, GEMM_SMEM_B>>>(
        p_act, p_womlp, p_h, out, MROWS, DM, INTER, DM, 1);
}

// round 17
// speedup vs baseline: 1.9316x; 1.0483x over previous
#include <cuda_runtime.h>
#include <cuda_bf16.h>
#include <math.h>
#include <stdint.h>
#include <string.h>

#define Bsz 4
#define SEQ 2048
#define DM 768
#define NH 12
#define DH 64
#define INTER 1152
#define MROWS (Bsz*SEQ)   // 8192

// ---------------- scratch (allocation-free) ----------------
__device__ float g_qkv[MROWS*3*DM];
__device__ float g_h  [MROWS*DM];
__device__ float g_tmp[MROWS*INTER];            // x half of wi output (fp32)
__device__ __nv_bfloat16 g_xn_bf [MROWS*DM];
__device__ __nv_bfloat16 g_ctx_bf[MROWS*DM];
__device__ __nv_bfloat16 g_act_bf[MROWS*INTER];
__device__ __nv_bfloat16 g_wqkv_bf[DM*3*DM];
__device__ __nv_bfloat16 g_wo_bf  [DM*DM];
__device__ __nv_bfloat16 g_wi_bf  [DM*2*INTER];
__device__ __nv_bfloat16 g_womlp_bf[INTER*DM];

__device__ __forceinline__ uint32_t bf2_bits(__nv_bfloat162 v) {
    uint32_t u;
    memcpy(&u, &v, 4);
    return u;
}

__device__ __forceinline__ void cp16(uint32_t s, const void* g) {
    asm volatile("cp.async.cg.shared.global [%0], [%1], 16;\n" :: "r"(s), "l"(g));
}
#define CP_COMMIT() asm volatile("cp.async.commit_group;\n" ::: "memory")
#define CP_WAIT(n)  asm volatile("cp.async.wait_group %0;\n" :: "n"(n) : "memory")

// ---------------- merged weight convert ----------------
#define WC_S1 (DM*3*DM)
#define WC_S2 (DM*DM)
#define WC_S3 (DM*2*INTER)
#define WC_S4 (INTER*DM)
#define WC_TOTAL (WC_S1+WC_S2+WC_S3+WC_S4)

__global__ void wconv_kernel(const float* __restrict__ w1, const float* __restrict__ w2,
                             const float* __restrict__ w3, const float* __restrict__ w4,
                             __nv_bfloat16* __restrict__ o1, __nv_bfloat16* __restrict__ o2,
                             __nv_bfloat16* __restrict__ o3, __nv_bfloat16* __restrict__ o4) {
    int i = (blockIdx.x * blockDim.x + threadIdx.x) * 4;
    if (i >= WC_TOTAL) return;
    const float* in; __nv_bfloat16* out; int off;
    if (i < WC_S1)                       { in = w1; out = o1; off = i; }
    else if (i < WC_S1+WC_S2)            { in = w2; out = o2; off = i - WC_S1; }
    else if (i < WC_S1+WC_S2+WC_S3)      { in = w3; out = o3; off = i - WC_S1 - WC_S2; }
    else                                 { in = w4; out = o4; off = i - WC_S1 - WC_S2 - WC_S3; }
    float4 v = *(const float4*)(in + off);
    *(__nv_bfloat162*)(out + off)     = __floats2bfloat162_rn(v.x, v.y);
    *(__nv_bfloat162*)(out + off + 2) = __floats2bfloat162_rn(v.z, v.w);
}

// ---------------- block reduce ----------------
__device__ __forceinline__ float blockReduceSum(float val, float* sh) {
    __syncthreads();
    int lane = threadIdx.x & 31, w = threadIdx.x >> 5;
    #pragma unroll
    for (int o = 16; o; o >>= 1) val += __shfl_xor_sync(0xffffffffu, val, o);
    if (lane == 0) sh[w] = val;
    __syncthreads();
    if (w == 0) {
        float v = (lane < 8) ? sh[lane] : 0.f;
        #pragma unroll
        for (int o = 4; o; o >>= 1) v += __shfl_xor_sync(0xffffffffu, v, o);
        if (lane == 0) sh[0] = v;
    }
    __syncthreads();
    return sh[0];
}

// ---------------- layernorm (fp32 in, bf16 out) ----------------
__global__ void ln_kernel(const float* __restrict__ x, const float* __restrict__ gamma,
                          __nv_bfloat16* __restrict__ out) {
    __shared__ float sh[8];
    int row = blockIdx.x;
    const float* xr = x + (size_t)row * DM;
    int t = threadIdx.x;
    float v[3]; float s = 0.f;
    #pragma unroll
    for (int i = 0; i < 3; i++) { v[i] = xr[t + i*256]; s += v[i]; }
    float tot = blockReduceSum(s, sh);
    float mean = tot * (1.0f/768.0f);
    float s2 = 0.f;
    #pragma unroll
    for (int i = 0; i < 3; i++) { float d = v[i]-mean; s2 += d*d; }
    float tot2 = blockReduceSum(s2, sh);
    float rstd = rsqrtf(tot2 * (1.0f/768.0f) + 1e-5f);
    __nv_bfloat16* orow = out + (size_t)row * DM;
    #pragma unroll
    for (int i = 0; i < 3; i++)
        orow[t + i*256] = __float2bfloat16((v[i]-mean) * rstd * gamma[t + i*256]);
}

// ---------------- BF16 GEMM: 128x128, warp 64x32, 5-stage ----------------
// mode 0: C fp32 = AB     mode 1: C fp32 = AB + R     mode 2: C bf16 = gelu(R)*AB
#define BM 128
#define BN 128
#define BK 32
#define NST 5
#define ASTRh 40
#define BSTRh 136
#define A_STAGE_H (BM*ASTRh)
#define B_STAGE_H (BK*BSTRh)
#define AOFFh (NST*A_STAGE_H)
#define GEMM_SMEM_B ((AOFFh + NST*B_STAGE_H)*2)   // 94720 bytes

__global__ void __launch_bounds__(256, 2)
bf16gemm_kernel(const __nv_bfloat16* __restrict__ A, const __nv_bfloat16* __restrict__ B,
                const float* __restrict__ R, void* __restrict__ Cv,
                int M, int N, int K, int ldB, int mode) {
    extern __shared__ __nv_bfloat16 smem[];
    uint32_t sBase = (uint32_t)__cvta_generic_to_shared(smem);

    int tid = threadIdx.x;
    int lane = tid & 31, warp = tid >> 5;
    int wm = warp >> 2, wn = warp & 3;
    int bm = blockIdx.y * BM, bn = blockIdx.x * BN;
    int lr = lane >> 2, lc = lane & 3;

    float acc[4][4][4];
    #pragma unroll
    for (int i = 0; i < 4; i++)
        #pragma unroll
        for (int j = 0; j < 4; j++)
            #pragma unroll
            for (int r = 0; r < 4; r++) acc[i][j][r] = 0.f;

    auto issue = [&](int kblk, int slot) {
        #pragma unroll
        for (int i = 0; i < 2; i++) {
            int c = tid*2 + i;
            int row = c >> 2, koff = (c & 3) * 8;
            const __nv_bfloat16* g = A + (size_t)(bm + row) * K + kblk + koff;
            cp16(sBase + (slot*A_STAGE_H + row*ASTRh + koff)*2, g);
        }
        #pragma unroll
        for (int i = 0; i < 2; i++) {
            int c = tid*2 + i;
            int row = c >> 4, noff = (c & 15) * 8;
            const __nv_bfloat16* g = B + (size_t)(kblk + row) * ldB + bn + noff;
            cp16(sBase + (AOFFh + slot*B_STAGE_H + row*BSTRh + noff)*2, g);
        }
    };

    int nk = K / BK;
    #pragma unroll
    for (int s = 0; s < NST-1; s++) { issue(s*BK, s); CP_COMMIT(); }

    int aRowSel = lane & 15;
    int aColSel = (lane >> 4) << 3;
    int bKSel   = (lane & 7) + ((lane >> 4) << 3);
    int bNSel   = ((lane >> 3) & 1) << 3;

    for (int s = 0; s < nk; s++) {
        CP_WAIT(NST-2);
        __syncthreads();
        int nxt = s + NST - 1;
        if (nxt < nk) issue(nxt*BK, nxt % NST);
        CP_COMMIT();

        int buf = s % NST;
        uint32_t aBase = sBase + (buf*A_STAGE_H)*2;
        uint32_t bBase = sBase + (AOFFh + buf*B_STAGE_H)*2;

        #pragma unroll
        for (int ks = 0; ks < 2; ks++) {
            int kb = ks * 16;
            uint32_t af[4][4], bfr[4][2];
            #pragma unroll
            for (int mt = 0; mt < 4; mt++) {
                int row = wm*64 + mt*16 + aRowSel;
                uint32_t addr = aBase + (row*ASTRh + kb + aColSel)*2;
                asm volatile("ldmatrix.sync.aligned.m8n8.x4.shared.b16 {%0,%1,%2,%3}, [%4];"
                    : "=r"(af[mt][0]), "=r"(af[mt][1]), "=r"(af[mt][2]), "=r"(af[mt][3])
                    : "r"(addr));
            }
            #pragma unroll
            for (int ntp = 0; ntp < 2; ntp++) {
                int krow = kb + bKSel;
                int ncol = wn*32 + ntp*16 + bNSel;
                uint32_t addr = bBase + (krow*BSTRh + ncol)*2;
                uint32_t r0, r1, r2, r3;
                asm volatile("ldmatrix.sync.aligned.m8n8.x4.trans.shared.b16 {%0,%1,%2,%3}, [%4];"
                    : "=r"(r0), "=r"(r1), "=r"(r2), "=r"(r3)
                    : "r"(addr));
                bfr[2*ntp][0]   = r0; bfr[2*ntp][1]   = r2;
                bfr[2*ntp+1][0] = r1; bfr[2*ntp+1][1] = r3;
            }
            #pragma unroll
            for (int mt = 0; mt < 4; mt++)
                #pragma unroll
                for (int nt = 0; nt < 4; nt++) {
                    asm volatile(
                        "mma.sync.aligned.m16n8k16.row.col.f32.bf16.bf16.f32 "
                        "{%0,%1,%2,%3},{%4,%5,%6,%7},{%8,%9},{%0,%1,%2,%3};"
                        : "+f"(acc[mt][nt][0]), "+f"(acc[mt][nt][1]),
                          "+f"(acc[mt][nt][2]), "+f"(acc[mt][nt][3])
                        : "r"(af[mt][0]), "r"(af[mt][1]), "r"(af[mt][2]), "r"(af[mt][3]),
                          "r"(bfr[nt][0]), "r"(bfr[nt][1]));
                }
        }
    }

    #pragma unroll
    for (int mt = 0; mt < 4; mt++) {
        int r0 = bm + wm*64 + mt*16 + lr;
        #pragma unroll
        for (int half = 0; half < 2; half++) {
            int row = r0 + half*8;
            #pragma unroll
            for (int nt = 0; nt < 4; nt++) {
                int col = bn + wn*32 + nt*8 + 2*lc;
                size_t off = (size_t)row * N + col;
                float a0 = acc[mt][nt][half*2], a1 = acc[mt][nt][half*2+1];
                if (mode == 2) {
                    float2 xv = *(const float2*)(R + off);
                    float v0 = xv.x * normcdff(xv.x) * a0;
                    float v1 = xv.y * normcdff(xv.y) * a1;
                    *(__nv_bfloat162*)((__nv_bfloat16*)Cv + off)
                        = __floats2bfloat162_rn(v0, v1);
                } else {
                    if (mode == 1) {
                        float2 rv = *(const float2*)(R + off);
                        a0 += rv.x; a1 += rv.y;
                    }
                    *(float2*)((float*)Cv + off) = make_float2(a0, a1);
                }
            }
        }
    }
}

// ---------------- RoPE ----------------
__global__ void rope_kernel(float* __restrict__ qkv) {
    int idx = blockIdx.x * blockDim.x + threadIdx.x;
    if (idx >= MROWS * NH * 32) return;
    int i   = idx & 31;
    int h   = (idx >> 5) % NH;
    int row = idx / (32 * NH);
    int s   = row & (SEQ - 1);
    float invf = expf(-(float)i * (9.210340371976184f / 32.0f));
    float ang = (float)s * invf;
    float c, sn;
    sincosf(ang, &sn, &c);
    size_t base = (size_t)row * (3*DM) + h * DH;
    float* q = qkv + base;
    float* k = qkv + base + DM;
    float q1 = q[i], q2 = q[i+32];
    q[i]    = q1*c - q2*sn;
    q[i+32] = q2*c + q1*sn;
    float k1 = k[i], k2 = k[i+32];
    k[i]    = k1*c - k2*sn;
    k[i+32] = k2*c + k1*sn;
}

// ---------------- BF16 MMA sliding-window attention ----------------
// 64 q/block, key span 192. Q in regs (bf16 A-frags), K/V bf16 smem,
// P (bf16) aliases K. m16n8k16 throughout; softmax in fp32.
#define TQ 64
#define TK 192
#define KSTRh 72
#define VSTRh 72
#define PSTRh 200
#define SMH_V_OFF (TK*KSTRh)                 // 13824 halves
#define SM_ATTN_H (SMH_V_OFF + TK*VSTRh)     // 27648 halves
#define SM_ATTN_BYTES (SM_ATTN_H*2)          // 55296 bytes

__global__ void __launch_bounds__(128, 2)
attn_mma_kernel(const float* __restrict__ qkv, __nv_bfloat16* __restrict__ ctx) {
    extern __shared__ __nv_bfloat16 smh[];
    uint32_t sBase = (uint32_t)__cvta_generic_to_shared(smh);
    __nv_bfloat16* Ks = smh;                 // [192][72]
    __nv_bfloat16* Ps = smh;                 // alias after QK phase [64][200]
    __nv_bfloat16* Vs = smh + SMH_V_OFF;     // [192][72]

    int bh = blockIdx.y;
    int b = bh / NH, h = bh % NH;
    int q0 = blockIdx.x * TQ;
    int kc0 = q0 - 64;
    int tid = threadIdx.x, lane = tid & 31, w = tid >> 5;
    int lr = lane >> 2, lc = lane & 3;

    size_t rowQ = (size_t)b * SEQ;
    size_t baseQ = rowQ * (3*DM) + h * DH;
    size_t baseK = baseQ + DM;
    size_t baseV = baseQ + 2*DM;

    // ---- Q A-fragments (m16n8k16): rows r0=16w+lr, r1=r0+8; scaled 1/8 ----
    uint32_t qf[4][4];
    {
        const float* qp0 = qkv + baseQ + (size_t)(q0 + 16*w + lr) * (3*DM);
        const float* qp1 = qp0 + (size_t)8 * (3*DM);
        #pragma unroll
        for (int ks = 0; ks < 4; ks++) {
            int d0 = 16*ks + 2*lc;
            float2 v00 = *(const float2*)(qp0 + d0);
            float2 v10 = *(const float2*)(qp1 + d0);
            float2 v01 = *(const float2*)(qp0 + d0 + 8);
            float2 v11 = *(const float2*)(qp1 + d0 + 8);
            qf[ks][0] = bf2_bits(__floats2bfloat162_rn(v00.x*0.125f, v00.y*0.125f));
            qf[ks][1] = bf2_bits(__floats2bfloat162_rn(v10.x*0.125f, v10.y*0.125f));
            qf[ks][2] = bf2_bits(__floats2bfloat162_rn(v01.x*0.125f, v01.y*0.125f));
            qf[ks][3] = bf2_bits(__floats2bfloat162_rn(v11.x*0.125f, v11.y*0.125f));
        }
    }

    // ---- load K, V (fp32 gmem -> bf16 smem) ----
    #pragma unroll
    for (int i = 0; i < 24; i++) {
        int id = tid + i*128;
        int r = id >> 4, c = (id & 15) << 2;
        int kg = kc0 + r;
        float4 kv = make_float4(0,0,0,0), vv = make_float4(0,0,0,0);
        if (kg >= 0 && kg < SEQ) {
            kv = *(const float4*)(qkv + baseK + (size_t)kg*(3*DM) + c);
            vv = *(const float4*)(qkv + baseV + (size_t)kg*(3*DM) + c);
        }
        __nv_bfloat162* pk = (__nv_bfloat162*)&Ks[r*KSTRh + c];
        pk[0] = __floats2bfloat162_rn(kv.x, kv.y);
        pk[1] = __floats2bfloat162_rn(kv.z, kv.w);
        __nv_bfloat162* pv = (__nv_bfloat162*)&Vs[r*VSTRh + c];
        pv[0] = __floats2bfloat162_rn(vv.x, vv.y);
        pv[1] = __floats2bfloat162_rn(vv.z, vv.w);
    }
    __syncthreads();

    // ---- QK^T (bf16 m16n8k16): warp w rows 16w..16w+15, 192 cols ----
    float acc[24][4];
    #pragma unroll
    for (int nt = 0; nt < 24; nt++)
        #pragma unroll
        for (int j = 0; j < 4; j++) acc[nt][j] = 0.f;

    #pragma unroll
    for (int ks = 0; ks < 4; ks++) {
        #pragma unroll
        for (int nt = 0; nt < 24; nt++) {
            uint32_t b0 = *(const uint32_t*)&Ks[(8*nt + lr)*KSTRh + 16*ks + 2*lc];
            uint32_t b1 = *(const uint32_t*)&Ks[(8*nt + lr)*KSTRh + 16*ks + 2*lc + 8];
            asm volatile(
                "mma.sync.aligned.m16n8k16.row.col.f32.bf16.bf16.f32 "
                "{%0,%1,%2,%3},{%4,%5,%6,%7},{%8,%9},{%0,%1,%2,%3};"
                : "+f"(acc[nt][0]), "+f"(acc[nt][1]), "+f"(acc[nt][2]), "+f"(acc[nt][3])
                : "r"(qf[ks][0]), "r"(qf[ks][1]), "r"(qf[ks][2]), "r"(qf[ks][3]),
                  "r"(b0), "r"(b1));
        }
    }

    // ---- mask + single-pass softmax (c-frag layout identical to k8) ----
    int r0 = 16*w + lr, r1 = r0 + 8;
    int cl0 = (q0 == 0) ? 64 : 0;
    int cl1 = SEQ - 1 - kc0; if (cl1 > 191) cl1 = 191;
    int lo0 = r0 > cl0 ? r0 : cl0;  int hi0 = (r0+128) < cl1 ? (r0+128) : cl1;
    int lo1 = r1 > cl0 ? r1 : cl0;  int hi1 = (r1+128) < cl1 ? (r1+128) : cl1;

    float m0 = -1e30f, m1 = -1e30f;
    #pragma unroll
    for (int nt = 0; nt < 24; nt++) {
        int c = 8*nt + 2*lc;
        if (c   >= lo0 && c   <= hi0) m0 = fmaxf(m0, acc[nt][0]);
        if (c+1 >= lo0 && c+1 <= hi0) m0 = fmaxf(m0, acc[nt][1]);
        if (c   >= lo1 && c   <= hi1) m1 = fmaxf(m1, acc[nt][2]);
        if (c+1 >= lo1 && c+1 <= hi1) m1 = fmaxf(m1, acc[nt][3]);
    }
    #pragma unroll
    for (int o = 1; o <= 2; o <<= 1) {
        m0 = fmaxf(m0, __shfl_xor_sync(0xffffffffu, m0, o));
        m1 = fmaxf(m1, __shfl_xor_sync(0xffffffffu, m1, o));
    }
    float l0 = 0.f, l1 = 0.f;
    #pragma unroll
    for (int nt = 0; nt < 24; nt++) {
        int c = 8*nt + 2*lc;
        float p;
        p = (c   >= lo0 && c   <= hi0) ? __expf(acc[nt][0] - m0) : 0.f; acc[nt][0] = p; l0 += p;
        p = (c+1 >= lo0 && c+1 <= hi0) ? __expf(acc[nt][1] - m0) : 0.f; acc[nt][1] = p; l0 += p;
        p = (c   >= lo1 && c   <= hi1) ? __expf(acc[nt][2] - m1) : 0.f; acc[nt][2] = p; l1 += p;
        p = (c+1 >= lo1 && c+1 <= hi1) ? __expf(acc[nt][3] - m1) : 0.f; acc[nt][3] = p; l1 += p;
    }
    #pragma unroll
    for (int o = 1; o <= 2; o <<= 1) {
        l0 += __shfl_xor_sync(0xffffffffu, l0, o);
        l1 += __shfl_xor_sync(0xffffffffu, l1, o);
    }
    float inv0 = 1.0f / l0, inv1 = 1.0f / l1;

    __syncthreads();   // all warps done reading Ks before P overwrites it

    #pragma unroll
    for (int nt = 0; nt < 24; nt++) {
        int c = 8*nt + 2*lc;
        *(__nv_bfloat162*)&Ps[r0*PSTRh + c] =
            __floats2bfloat162_rn(acc[nt][0]*inv0, acc[nt][1]*inv0);
        *(__nv_bfloat162*)&Ps[r1*PSTRh + c] =
            __floats2bfloat162_rn(acc[nt][2]*inv1, acc[nt][3]*inv1);
    }
    __syncthreads();

    // ---- P @ V (bf16 m16n8k16): 12 k-chunks of 16 keys, 8 n-tiles of 8 ----
    float o[8][4];
    #pragma unroll
    for (int nt = 0; nt < 8; nt++)
        #pragma unroll
        for (int j = 0; j < 4; j++) o[nt][j] = 0.f;

    int bKSel = (lane & 7) + ((lane >> 4) << 3);
    int bNSel = ((lane >> 3) & 1) << 3;

    #pragma unroll
    for (int ks2 = 0; ks2 < 12; ks2++) {
        int k0 = 16*ks2 + 2*lc;
        uint32_t a0 = *(const uint32_t*)&Ps[r0*PSTRh + k0];
        uint32_t a1 = *(const uint32_t*)&Ps[r1*PSTRh + k0];
        uint32_t a2 = *(const uint32_t*)&Ps[r0*PSTRh + k0 + 8];
        uint32_t a3 = *(const uint32_t*)&Ps[r1*PSTRh + k0 + 8];
        #pragma unroll
        for (int g = 0; g < 4; g++) {
            int krow = 16*ks2 + bKSel;
            int ncol = 16*g + bNSel;
            uint32_t addr = sBase + (SMH_V_OFF + krow*VSTRh + ncol)*2;
            uint32_t v0, v1, v2, v3;
            asm volatile("ldmatrix.sync.aligned.m8n8.x4.trans.shared.b16 {%0,%1,%2,%3}, [%4];"
                : "=r"(v0), "=r"(v1), "=r"(v2), "=r"(v3)
                : "r"(addr));
            asm volatile(
                "mma.sync.aligned.m16n8k16.row.col.f32.bf16.bf16.f32 "
                "{%0,%1,%2,%3},{%4,%5,%6,%7},{%8,%9},{%0,%1,%2,%3};"
                : "+f"(o[2*g][0]), "+f"(o[2*g][1]), "+f"(o[2*g][2]), "+f"(o[2*g][3])
                : "r"(a0), "r"(a1), "r"(a2), "r"(a3), "r"(v0), "r"(v2));
            asm volatile(
                "mma.sync.aligned.m16n8k16.row.col.f32.bf16.bf16.f32 "
                "{%0,%1,%2,%3},{%4,%5,%6,%7},{%8,%9},{%0,%1,%2,%3};"
                : "+f"(o[2*g+1][0]), "+f"(o[2*g+1][1]), "+f"(o[2*g+1][2]), "+f"(o[2*g+1][3])
                : "r"(a0), "r"(a1), "r"(a2), "r"(a3), "r"(v1), "r"(v3));
        }
    }

    size_t baseO = rowQ * DM + h * DH;
    int row0 = q0 + 16*w + lr;
    #pragma unroll
    for (int nt = 0; nt < 8; nt++) {
        int col = 8*nt + 2*lc;
        *(__nv_bfloat162*)(ctx + baseO + (size_t)row0 * DM + col)
            = __floats2bfloat162_rn(o[nt][0], o[nt][1]);
        *(__nv_bfloat162*)(ctx + baseO + (size_t)(row0+8) * DM + col)
            = __floats2bfloat162_rn(o[nt][2], o[nt][3]);
    }
}

// ---------------- launch ----------------
extern "C" void kernel_launch(void* const* d_in, const int* in_sizes, int n_in,
                              void* d_out, int out_size) {
    const float* hidden  = (const float*)d_in[0];
    const float* gamma1  = (const float*)d_in[2];
    const float* wqkv    = (const float*)d_in[3];
    const float* wo_attn = (const float*)d_in[4];
    const float* gamma2  = (const float*)d_in[5];
    const float* wi      = (const float*)d_in[6];
    const float* wo_mlp  = (const float*)d_in[7];
    float* out = (float*)d_out;

    static float *p_qkv=nullptr, *p_h, *p_tmp;
    static __nv_bfloat16 *p_xn, *p_ctx, *p_act, *p_wqkv, *p_wo, *p_wi, *p_womlp;
    if (!p_qkv) {
        cudaGetSymbolAddress((void**)&p_qkv, g_qkv);
        cudaGetSymbolAddress((void**)&p_h,   g_h);
        cudaGetSymbolAddress((void**)&p_tmp, g_tmp);
        cudaGetSymbolAddress((void**)&p_xn,  g_xn_bf);
        cudaGetSymbolAddress((void**)&p_ctx, g_ctx_bf);
        cudaGetSymbolAddress((void**)&p_act, g_act_bf);
        cudaGetSymbolAddress((void**)&p_wqkv, g_wqkv_bf);
        cudaGetSymbolAddress((void**)&p_wo,   g_wo_bf);
        cudaGetSymbolAddress((void**)&p_wi,   g_wi_bf);
        cudaGetSymbolAddress((void**)&p_womlp, g_womlp_bf);
        cudaFuncSetAttribute(attn_mma_kernel,
                             cudaFuncAttributeMaxDynamicSharedMemorySize, SM_ATTN_BYTES);
        cudaFuncSetAttribute(bf16gemm_kernel,
                             cudaFuncAttributeMaxDynamicSharedMemorySize, GEMM_SMEM_B);
    }

    wconv_kernel<<<(WC_TOTAL/4 + 255)/256, 256>>>(wqkv, wo_attn, wi, wo_mlp,
                                                  p_wqkv, p_wo, p_wi, p_womlp);
    ln_kernel<<<MROWS, 256>>>(hidden, gamma1, p_xn);
    bf16gemm_kernel<<<dim3(2304/BN, MROWS/BM), 256, GEMM_SMEM_B>>>(
        p_xn, p_wqkv, nullptr, p_qkv, MROWS, 3*DM, DM, 3*DM, 0);
    {
        int n = MROWS * NH * 32;
        rope_kernel<<<(n + 255)/256, 256>>>(p_qkv);
    }
    attn_mma_kernel<<<dim3(SEQ/TQ, Bsz*NH), 128, SM_ATTN_BYTES>>>(p_qkv, p_ctx);
    bf16gemm_kernel<<<dim3(DM/BN, MROWS/BM), 256, GEMM_SMEM_B>>>(
        p_ctx, p_wo, hidden, p_h, MROWS, DM, DM, DM, 1);
    ln_kernel<<<MROWS, 256>>>(p_h, gamma2, p_xn);
    bf16gemm_kernel<<<dim3(INTER/BN, MROWS/BM), 256, GEMM_SMEM_B>>>(
        p_xn, p_wi, nullptr, p_tmp, MROWS, INTER, DM, 2*INTER, 0);
    bf16gemm_kernel<<<dim3(INTER/BN, MROWS/BM), 256, GEMM_SMEM_B>>>(
        p_xn, p_wi + INTER, p_tmp, p_act, MROWS, INTER, DM, 2*INTER, 2);
    bf16gemm_kernel<<<dim3(DM/BN, MROWS/BM), 256, GEMM_SMEM_B>>>(
        p_act, p_womlp, p_h, out, MROWS, DM, INTER, DM, 1);
}